// round 16
// baseline (speedup 1.0000x reference)
#include <cuda_runtime.h>
#include <math.h>

#define HCH  512
#define NST  64
#define BS   8
#define LSEQ 2048
#define NFFT 4096
#define SIDX(i) ((i) + ((i) >> 4))
#define SPAD (NFFT + (NFFT >> 4))   // 4352 float2 = 34816 B

// per-channel spectrum, layout [h][j*256 + t] holding bit-rev position p=16t+j
__device__ float2 d_Kf[(size_t)HCH * NFFT];
// per-channel ready flags (reset every launch by zero_flags)
__device__ int d_flags[HCH];

// W16^m = exp(-2*pi*i*m/16), m=0..7
__constant__ float2 C16[8] = {
    { 1.0f,           0.0f},
    { 0.92387953251f, -0.38268343236f},
    { 0.70710678119f, -0.70710678119f},
    { 0.38268343236f, -0.92387953251f},
    { 0.0f,          -1.0f},
    {-0.38268343236f, -0.92387953251f},
    {-0.70710678119f, -0.70710678119f},
    {-0.92387953251f, -0.38268343236f},
};
// W8^m = exp(-2*pi*i*m/8), m=0..3
__constant__ float2 C8[4] = {
    { 1.0f,           0.0f},
    { 0.70710678119f, -0.70710678119f},
    { 0.0f,          -1.0f},
    {-0.70710678119f, -0.70710678119f},
};

typedef unsigned long long u64c;

// ---- packed f32x2 helpers (sm_100a) ----
__device__ __forceinline__ u64c pk2(float lo, float hi) {
    u64c r; asm("mov.b64 %0, {%1, %2};" : "=l"(r) : "f"(lo), "f"(hi)); return r;
}
__device__ __forceinline__ float2 unpk2(u64c v) {
    float lo, hi; asm("mov.b64 {%0, %1}, %2;" : "=f"(lo), "=f"(hi) : "l"(v));
    return make_float2(lo, hi);
}
__device__ __forceinline__ u64c ffma2_(u64c a, u64c b, u64c c) {
    u64c r; asm("fma.rn.f32x2 %0, %1, %2, %3;" : "=l"(r) : "l"(a), "l"(b), "l"(c));
    return r;
}
__device__ __forceinline__ u64c fadd2_(u64c a, u64c b) {
    u64c r; asm("add.rn.f32x2 %0, %1, %2;" : "=l"(r) : "l"(a), "l"(b));
    return r;
}

__device__ __forceinline__ float2 cmul(float2 a, float2 b) {
    return make_float2(fmaf(a.x, b.x, -a.y * b.y), fmaf(a.x, b.y, a.y * b.x));
}
__device__ __forceinline__ float2 cmulj(float2 a, float2 b) {   // a * conj(b)
    return make_float2(fmaf(a.x, b.x, a.y * b.y), fmaf(a.y, b.x, -a.x * b.y));
}
__device__ __forceinline__ float2 cadd(float2 a, float2 b) { return make_float2(a.x + b.x, a.y + b.y); }
__device__ __forceinline__ float2 csub(float2 a, float2 b) { return make_float2(a.x - b.x, a.y - b.y); }

__device__ __forceinline__ float2 tw4096(int j) {
    float s, c;
    sincospif((float)j * (1.0f / 2048.0f), &s, &c);
    return make_float2(c, -s);
}
__device__ __forceinline__ float2 tw2048(int j) {
    float s, c;
    sincospif((float)j * (1.0f / 1024.0f), &s, &c);
    return make_float2(c, -s);
}

// ---------------------------------------------------------------------------
// Register FFT blocks. fwd16/inv16 = 4 radix-2 DIF/DIT stages; fwd8/inv8 = 3.
// Composition of DIF passes => position p holds frequency brev(p).
// ---------------------------------------------------------------------------
__device__ __forceinline__ void fwd16(float2* v, float2 w1) {
    float2 w2 = cmul(w1, w1), w4 = cmul(w2, w2), w8 = cmul(w4, w4);
#pragma unroll
    for (int j = 0; j < 8; j++) {
        float2 tw = cmul(w1, C16[j]);
        float2 a = v[j], bb = v[j + 8];
        v[j] = cadd(a, bb);
        v[j + 8] = cmul(csub(a, bb), tw);
    }
#pragma unroll
    for (int g = 0; g < 16; g += 8)
#pragma unroll
        for (int j = 0; j < 4; j++) {
            float2 tw = cmul(w2, C16[2 * j]);
            float2 a = v[g + j], bb = v[g + j + 4];
            v[g + j] = cadd(a, bb);
            v[g + j + 4] = cmul(csub(a, bb), tw);
        }
#pragma unroll
    for (int g = 0; g < 16; g += 4)
#pragma unroll
        for (int j = 0; j < 2; j++) {
            float2 tw = cmul(w4, C16[4 * j]);
            float2 a = v[g + j], bb = v[g + j + 2];
            v[g + j] = cadd(a, bb);
            v[g + j + 2] = cmul(csub(a, bb), tw);
        }
#pragma unroll
    for (int g = 0; g < 16; g += 2) {
        float2 a = v[g], bb = v[g + 1];
        v[g] = cadd(a, bb);
        v[g + 1] = cmul(csub(a, bb), w8);
    }
}

// Zero-padded variant: v[8..15] implicitly zero on entry (not read).
__device__ __forceinline__ void fwd16z(float2* v, float2 w1) {
    float2 w2 = cmul(w1, w1), w4 = cmul(w2, w2), w8 = cmul(w4, w4);
#pragma unroll
    for (int j = 0; j < 8; j++) {
        float2 tw = cmul(w1, C16[j]);
        v[j + 8] = cmul(v[j], tw);     // a + 0, (a - 0)*tw
    }
#pragma unroll
    for (int g = 0; g < 16; g += 8)
#pragma unroll
        for (int j = 0; j < 4; j++) {
            float2 tw = cmul(w2, C16[2 * j]);
            float2 a = v[g + j], bb = v[g + j + 4];
            v[g + j] = cadd(a, bb);
            v[g + j + 4] = cmul(csub(a, bb), tw);
        }
#pragma unroll
    for (int g = 0; g < 16; g += 4)
#pragma unroll
        for (int j = 0; j < 2; j++) {
            float2 tw = cmul(w4, C16[4 * j]);
            float2 a = v[g + j], bb = v[g + j + 2];
            v[g + j] = cadd(a, bb);
            v[g + j + 2] = cmul(csub(a, bb), tw);
        }
#pragma unroll
    for (int g = 0; g < 16; g += 2) {
        float2 a = v[g], bb = v[g + 1];
        v[g] = cadd(a, bb);
        v[g + 1] = cmul(csub(a, bb), w8);
    }
}

__device__ __forceinline__ void inv16(float2* v, float2 w1) {
    float2 c1 = make_float2(w1.x, -w1.y);
    float2 c2 = cmul(c1, c1), c4 = cmul(c2, c2), c8 = cmul(c4, c4);
#pragma unroll
    for (int g = 0; g < 16; g += 2) {
        float2 tb = cmul(v[g + 1], c8);
        float2 a = v[g];
        v[g] = cadd(a, tb);
        v[g + 1] = csub(a, tb);
    }
#pragma unroll
    for (int g = 0; g < 16; g += 4)
#pragma unroll
        for (int j = 0; j < 2; j++) {
            float2 tw = cmulj(c4, C16[4 * j]);
            float2 tb = cmul(v[g + j + 2], tw);
            float2 a = v[g + j];
            v[g + j] = cadd(a, tb);
            v[g + j + 2] = csub(a, tb);
        }
#pragma unroll
    for (int g = 0; g < 16; g += 8)
#pragma unroll
        for (int j = 0; j < 4; j++) {
            float2 tw = cmulj(c2, C16[2 * j]);
            float2 tb = cmul(v[g + j + 4], tw);
            float2 a = v[g + j];
            v[g + j] = cadd(a, tb);
            v[g + j + 4] = csub(a, tb);
        }
#pragma unroll
    for (int j = 0; j < 8; j++) {
        float2 tw = cmulj(c1, C16[j]);
        float2 tb = cmul(v[j + 8], tw);
        float2 a = v[j];
        v[j] = cadd(a, tb);
        v[j + 8] = csub(a, tb);
    }
}

__device__ __forceinline__ void fwd8(float2* v, float2 w1) {
    float2 w2 = cmul(w1, w1), w4 = cmul(w2, w2);
#pragma unroll
    for (int j = 0; j < 4; j++) {
        float2 tw = cmul(w1, C8[j]);
        float2 a = v[j], bb = v[j + 4];
        v[j] = cadd(a, bb);
        v[j + 4] = cmul(csub(a, bb), tw);
    }
#pragma unroll
    for (int g = 0; g < 8; g += 4)
#pragma unroll
        for (int j = 0; j < 2; j++) {
            float2 tw = cmul(w2, C8[2 * j]);
            float2 a = v[g + j], bb = v[g + j + 2];
            v[g + j] = cadd(a, bb);
            v[g + j + 2] = cmul(csub(a, bb), tw);
        }
#pragma unroll
    for (int g = 0; g < 8; g += 2) {
        float2 a = v[g], bb = v[g + 1];
        v[g] = cadd(a, bb);
        v[g + 1] = cmul(csub(a, bb), w4);
    }
}

__device__ __forceinline__ void inv8(float2* v, float2 w1) {
    float2 c1 = make_float2(w1.x, -w1.y);
    float2 c2 = cmul(c1, c1), c4 = cmul(c2, c2);
#pragma unroll
    for (int g = 0; g < 8; g += 2) {
        float2 tb = cmul(v[g + 1], c4);
        float2 a = v[g];
        v[g] = cadd(a, tb);
        v[g + 1] = csub(a, tb);
    }
#pragma unroll
    for (int g = 0; g < 8; g += 4)
#pragma unroll
        for (int j = 0; j < 2; j++) {
            float2 tw = cmulj(c2, C8[2 * j]);
            float2 tb = cmul(v[g + j + 2], tw);
            float2 a = v[g + j];
            v[g + j] = cadd(a, tb);
            v[g + j + 2] = csub(a, tb);
        }
#pragma unroll
    for (int j = 0; j < 4; j++) {
        float2 tw = cmulj(c1, C8[j]);
        float2 tb = cmul(v[j + 4], tw);
        float2 a = v[j];
        v[j] = cadd(a, tb);
        v[j + 4] = csub(a, tb);
    }
}

// One full 4096 FFT-conv-IFFT on v[16] through smem x.
// Input: v[0..7] data, v[8..15] implicitly zero (zero-padded signal).
__device__ __forceinline__ void fft_conv_4096(
        float2* v, float2* x, int t, int base2,
        float2 w1, float2 wp2, const float2* __restrict__ kf) {
    fwd16z(v, w1);
#pragma unroll
    for (int j = 0; j < 16; j++) x[SIDX(t + 256 * j)] = v[j];
    __syncthreads();
#pragma unroll
    for (int j = 0; j < 16; j++) v[j] = x[SIDX(base2 + 16 * j)];
    fwd16(v, wp2);
#pragma unroll
    for (int j = 0; j < 16; j++) x[SIDX(base2 + 16 * j)] = v[j];
    __syncthreads();
#pragma unroll
    for (int j = 0; j < 16; j++) v[j] = x[SIDX(16 * t + j)];
    fwd16(v, make_float2(1.f, 0.f));
#pragma unroll
    for (int j = 0; j < 16; j++) v[j] = cmul(v[j], kf[j * 256 + t]);
    inv16(v, make_float2(1.f, 0.f));
#pragma unroll
    for (int j = 0; j < 16; j++) x[SIDX(16 * t + j)] = v[j];
    __syncthreads();
#pragma unroll
    for (int j = 0; j < 16; j++) v[j] = x[SIDX(base2 + 16 * j)];
    inv16(v, wp2);
#pragma unroll
    for (int j = 0; j < 16; j++) x[SIDX(base2 + 16 * j)] = v[j];
    __syncthreads();
#pragma unroll
    for (int j = 0; j < 16; j++) v[j] = x[SIDX(t + 256 * j)];
    inv16(v, w1);
}

// ---------------------------------------------------------------------------
__global__ void zero_flags() {
    if (threadIdx.x < HCH) d_flags[threadIdx.x] = 0;
}

// ---------------------------------------------------------------------------
// Fused kernel: bids [0, HCH) = spec; bids [HCH, HCH+1024) = conv (flag-gated).
// __launch_bounds__(256, 3): 85-reg cap so 3 CTAs/SM (24 warps; occupancy fix
// with NO added smem traffic — conv restructured as 2-channel loop without
// z1/y0 register parking).
// ---------------------------------------------------------------------------
__global__ void __launch_bounds__(256, 3) fused_kernel(
        const float* __restrict__ u,
        const float* __restrict__ Lr, const float* __restrict__ Li,
        const float* __restrict__ Pr, const float* __restrict__ Pi,
        const float* __restrict__ Br, const float* __restrict__ Bi,
        const float* __restrict__ Cr, const float* __restrict__ Ci,
        const float* __restrict__ logdt, const float* __restrict__ D,
        float* __restrict__ y) {
    extern __shared__ float2 x[];   // SPAD float2

    if (blockIdx.x < HCH) {
        // ================= SPEC branch =================
        const int h   = blockIdx.x;
        const int tid = threadIdx.x;

        __shared__ float2 lam[NST], w00[NST];
        __shared__ __align__(16) u64c WT[NST * 14];

        if (tid < NST) {
            int n = tid;
            lam[n] = make_float2(Lr[n], Li[n]);
            float2 P  = make_float2(Pr[n], Pi[n]);
            float2 Bv = make_float2(Br[n], Bi[n]);
            float2 Cc = make_float2(Cr[h * NST + n], -Ci[h * NST + n]);
            w00[n] = cmul(Cc, Bv);
        }
        __syncthreads();
        // Build packed a/b weight tables (a-lane n, b-lane m=63-n)
        if (tid < NST) {
            int n = tid, m = NST - 1 - n;
            u64c* T = &WT[n * 14];
            float2 Pn = make_float2(Pr[n], Pi[n]);
            float2 Pm = make_float2(Pr[m], Pi[m]);
            float2 Bn = make_float2(Br[n], Bi[n]);
            float2 Bm = make_float2(Br[m], Bi[m]);
            float2 Ccn = make_float2(Cr[h * NST + n], -Ci[h * NST + n]);
            float2 Ccm = make_float2(Cr[h * NST + m], -Ci[h * NST + m]);
            float2 wn, wm;
            wn = cmul(Ccn, Bn); wm = cmul(Ccm, Bm);          // w00
            T[0]  = pk2(wn.x, wm.x);  T[1]  = pk2(-wn.y, wm.y);
            T[2]  = pk2(wn.x, -wm.x); T[3]  = pk2(wn.y, wm.y);
            wn = cmul(Ccn, Pn); wm = cmul(Ccm, Pm);          // w01
            T[4]  = pk2(wn.x, wm.x);  T[5]  = pk2(-wn.y, wm.y);
            T[6]  = pk2(wn.x, -wm.x); T[7]  = pk2(wn.y, wm.y);
            float2 Qcn = make_float2(Pn.x, -Pn.y);
            float2 Qcm = make_float2(Pm.x, -Pm.y);
            wn = cmul(Qcn, Bn); wm = cmul(Qcm, Bm);          // w10
            T[8]  = pk2(wn.x, wm.x);  T[9]  = pk2(-wn.y, wm.y);
            T[10] = pk2(wn.x, -wm.x); T[11] = pk2(wn.y, wm.y);
            float w11n = Pn.x * Pn.x + Pn.y * Pn.y;
            float w11m = Pm.x * Pm.x + Pm.y * Pm.y;
            T[12] = pk2(w11n, w11m);
            T[13] = pk2(w11n, -w11m);
        }
        __syncthreads();

        const float dt = expf(logdt[h]);
        const float g0 = 2.0f / dt;

        // ---- Ã(l) = (A(l)+conj(A(2048-l)))/2, stored at brev11 positions ----
        for (int l = tid; l < 1024; l += blockDim.x) {
            float ss, cc;
            sincospif((float)l * (1.0f / 1024.0f), &ss, &cc);
            float2 om = make_float2(cc, -ss);
            float2 den = make_float2(1.f + om.x, om.y);
            float2 num = make_float2(1.f - om.x, -om.y);
            float idl  = __fdividef(1.f, den.x * den.x + den.y * den.y);
            float2 c2  = make_float2(2.f * den.x * idl, -2.f * den.y * idl);
            float2 gf  = cmul(num, make_float2(den.x, -den.y));
            float2 g   = make_float2(g0 * gf.x * idl, g0 * gf.y * idl);

            u64c K00R = 0, K00I = 0, K01R = 0, K01I = 0;
            u64c K10R = 0, K10I = 0, K11R = 0, K11I = 0;
#pragma unroll 4
            for (int n = 0; n < NST; n++) {
                float2 L = lam[n];
                float dx = g.x - L.x;
                float dy = g.y - L.y;
                float iv = __fdividef(1.f, fmaf(dx, dx, dy * dy));
                float rx = dx * iv;
                float ry = -dy * iv;
                u64c RX = pk2(rx, rx);
                u64c RY = pk2(ry, ry);
                const u64c* T = &WT[n * 14];
                ulonglong2 t0 = *(const ulonglong2*)(T + 0);
                ulonglong2 t1 = *(const ulonglong2*)(T + 2);
                ulonglong2 t2 = *(const ulonglong2*)(T + 4);
                ulonglong2 t3 = *(const ulonglong2*)(T + 6);
                ulonglong2 t4 = *(const ulonglong2*)(T + 8);
                ulonglong2 t5 = *(const ulonglong2*)(T + 10);
                ulonglong2 t6 = *(const ulonglong2*)(T + 12);
                K00R = ffma2_(t0.x, RX, K00R);  K00R = ffma2_(t0.y, RY, K00R);
                K00I = ffma2_(t1.x, RY, K00I);  K00I = ffma2_(t1.y, RX, K00I);
                K01R = ffma2_(t2.x, RX, K01R);  K01R = ffma2_(t2.y, RY, K01R);
                K01I = ffma2_(t3.x, RY, K01I);  K01I = ffma2_(t3.y, RX, K01I);
                K10R = ffma2_(t4.x, RX, K10R);  K10R = ffma2_(t4.y, RY, K10R);
                K10I = ffma2_(t5.x, RY, K10I);  K10I = ffma2_(t5.y, RX, K10I);
                K11R = ffma2_(t6.x, RX, K11R);
                K11I = ffma2_(t6.y, RY, K11I);
            }
            float2 r00 = unpk2(K00R), i00 = unpk2(K00I);
            float2 r01 = unpk2(K01R), i01 = unpk2(K01I);
            float2 r10 = unpk2(K10R), i10 = unpk2(K10I);
            float2 r11 = unpk2(K11R), i11 = unpk2(K11I);
            float2 a00 = make_float2(r00.x, i00.x), b00 = make_float2(r00.y, i00.y);
            float2 a01 = make_float2(r01.x, i01.x), b01 = make_float2(r01.y, i01.y);
            float2 a10 = make_float2(r10.x, i10.x), b10 = make_float2(r10.y, i10.y);
            float2 a11 = make_float2(r11.x, i11.x), b11 = make_float2(r11.y, i11.y);

            float2 Aa;
            {   // A[l]
                float2 onep = make_float2(1.f + a11.x, a11.y);
                float  ip   = __fdividef(1.f, onep.x * onep.x + onep.y * onep.y);
                float2 invd = make_float2(onep.x * ip, -onep.y * ip);
                float2 t2   = cmul(cmul(a01, a10), invd);
                Aa = cmul(c2, csub(a00, t2));
            }
            if (l != 0) {
                float2 Ab;   // A[2048-l]
                float2 c2c  = make_float2(c2.x, -c2.y);
                float2 onep = make_float2(1.f + b11.x, b11.y);
                float  ip   = __fdividef(1.f, onep.x * onep.x + onep.y * onep.y);
                float2 invd = make_float2(onep.x * ip, -onep.y * ip);
                float2 t2   = cmul(cmul(b01, b10), invd);
                Ab = cmul(c2c, csub(b00, t2));
                // Hermitian projection: Ã(l), Ã(2048-l)=conj(Ã(l))
                float2 At = make_float2(0.5f * (Aa.x + Ab.x), 0.5f * (Aa.y - Ab.y));
                int rl  = __brev(l) >> 21;
                int rl2 = __brev(2048 - l) >> 21;
                x[SIDX(rl)]  = At;
                x[SIDX(rl2)] = make_float2(At.x, -At.y);
            } else {
                x[SIDX(0)] = make_float2(Aa.x, 0.f);
            }
        }
        if (tid == 0) {
            // l = 1024: omega = -1 limit; Ã(1024) = Re(A(1024)); brev11(1024)=1
            float2 s = make_float2(0.f, 0.f);
            for (int n = 0; n < NST; n++) s = cadd(s, w00[n]);
            x[SIDX(1)] = make_float2(0.5f * dt * s.x, 0.f);
        }
        __syncthreads();

        float2* kf = d_Kf + (size_t)h * NFFT;

        // ---- EVEN half of K^: kf[j*256+t] = Ã at position p=16t+j (t<128) ----
#pragma unroll
        for (int s = 0; s < 8; s++) {
            int e  = tid + 256 * s;          // 0..2047
            int j  = e >> 7;                 // 0..15
            int tt = e & 127;                // 0..127
            kf[j * 256 + tt] = x[SIDX(16 * tt + j)];
        }
        __syncthreads();

        // ---- IFFT-2048 (inv8 {8t+j}, inv16 {baseB+8j}, inv16 {t+128j}) ----
        {
            float2 v8[8];
#pragma unroll
            for (int j = 0; j < 8; j++) v8[j] = x[SIDX(8 * tid + j)];
            inv8(v8, make_float2(1.f, 0.f));
#pragma unroll
            for (int j = 0; j < 8; j++) x[SIDX(8 * tid + j)] = v8[j];
        }
        __syncthreads();
        {
            float2 v[16];
            if (tid < 128) {
                int baseB = ((tid >> 3) << 7) + (tid & 7);
#pragma unroll
                for (int j = 0; j < 16; j++) v[j] = x[SIDX(baseB + 8 * j)];
                inv16(v, tw2048(16 * (tid & 7)));
#pragma unroll
                for (int j = 0; j < 16; j++) x[SIDX(baseB + 8 * j)] = v[j];
            }
            __syncthreads();
            if (tid < 128) {
#pragma unroll
                for (int j = 0; j < 16; j++) v[j] = x[SIDX(tid + 128 * j)];
                inv16(v, tw2048(tid));
                // scale + realify + modulate by W4096^n (n = tid + 128*j)
                const float  sc   = 1.0f / 2048.0f;
                const float2 C128 = make_float2(0.98078528040323044913f,
                                                -0.19509032201612826785f); // W4096^128
                float2 wn = tw4096(tid);
#pragma unroll
                for (int j = 0; j < 16; j++) {
                    float kk = v[j].x * sc;
                    x[SIDX(tid + 128 * j)] = make_float2(kk * wn.x, kk * wn.y);
                    wn = cmul(wn, C128);
                }
            }
        }
        __syncthreads();

        // ---- forward FFT-2048 on modulated K (natural -> brev11 positions) ----
        {
            float2 v[16];
            if (tid < 128) {
#pragma unroll
                for (int j = 0; j < 16; j++) v[j] = x[SIDX(tid + 128 * j)];
                fwd16(v, tw2048(tid));
#pragma unroll
                for (int j = 0; j < 16; j++) x[SIDX(tid + 128 * j)] = v[j];
            }
            __syncthreads();
            if (tid < 128) {
                int baseB = ((tid >> 3) << 7) + (tid & 7);
#pragma unroll
                for (int j = 0; j < 16; j++) v[j] = x[SIDX(baseB + 8 * j)];
                fwd16(v, tw2048((tid & 7) << 4));
#pragma unroll
                for (int j = 0; j < 16; j++) x[SIDX(baseB + 8 * j)] = v[j];
            }
            __syncthreads();
        }
        {
            float2 v8[8];
#pragma unroll
            for (int j = 0; j < 8; j++) v8[j] = x[SIDX(8 * tid + j)];
            fwd8(v8, make_float2(1.f, 0.f));
            // ---- ODD half of K^: position q=8*tid+j -> kf[(q&15)*256+128+(q>>4)]
#pragma unroll
            for (int j = 0; j < 8; j++) {
                int q = 8 * tid + j;
                kf[(q & 15) * 256 + 128 + (q >> 4)] = v8[j];
            }
        }

        // release
        __syncthreads();
        if (tid == 0) {
            __threadfence();
            atomicExch(&d_flags[h], 1);
        }
    } else {
        // ================= CONV branch =================
        // Two-iteration channel loop; no z1/y0 register parking.
        const int i  = blockIdx.x - HCH;
        const int hp = i & (HCH / 2 - 1);      // 0..255
        const int bp = i >> 8;                 // 0..3
        const int t  = threadIdx.x;

        if (t == 0) {
            while (atomicAdd(&d_flags[2 * hp], 0) == 0) __nanosleep(200);
            while (atomicAdd(&d_flags[2 * hp + 1], 0) == 0) __nanosleep(200);
            __threadfence();
        }
        __syncthreads();

        const float2* ua2 = (const float2*)(u + (size_t)(2 * bp) * LSEQ * HCH) + hp;
        const float2* ub2 = (const float2*)(u + (size_t)(2 * bp + 1) * LSEQ * HCH) + hp;
        float* ya = y + (size_t)(2 * bp) * LSEQ * HCH;
        float* yb = y + (size_t)(2 * bp + 1) * LSEQ * HCH;

        const float2 w1  = tw4096(t);
        const float2 wp2 = tw4096((t & 15) << 4);
        const int base2  = ((t >> 4) << 8) + (t & 15);
        const float inv  = 1.0f / (float)NFFT;

        for (int c = 0; c < 2; c++) {
            const int ch = 2 * hp + c;
            float2 v[16];
#pragma unroll
            for (int j = 0; j < 8; j++) {
                size_t idx = (size_t)(t + 256 * j) * (HCH / 2);
                float2 la = ua2[idx];
                float2 lb = ub2[idx];
                v[j] = (c == 0) ? make_float2(la.x, lb.x)
                                : make_float2(la.y, lb.y);   // b0 + i*b1
            }
            // v[8..15] implicitly zero (fwd16z)
            fft_conv_4096(v, x, t, base2, w1, wp2, d_Kf + (size_t)ch * NFFT);

            // epilogue for channel ch (scalar 4B stores; adjacent-channel
            // stores coalesce into the same sectors across loop iterations)
            const float Dc = D[ch];
#pragma unroll
            for (int j = 0; j < 8; j++) {
                int l = t + 256 * j;
                size_t idx = (size_t)l * (HCH / 2);
                float2 la = ua2[idx];
                float2 lb = ub2[idx];
                float uua = (c == 0) ? la.x : la.y;
                float uub = (c == 0) ? lb.x : lb.y;
                ya[(size_t)l * HCH + ch] = fmaf(v[j].x, inv, uua * Dc);
                yb[(size_t)l * HCH + ch] = fmaf(v[j].y, inv, uub * Dc);
            }
            // next iteration's first x write hits {t+256j}, same addresses as
            // this call's final read: no barrier needed (established R10+).
        }
    }
}

// ---------------------------------------------------------------------------
extern "C" void kernel_launch(void* const* d_in, const int* in_sizes, int n_in,
                              void* d_out, int out_size) {
    const float* u   = (const float*)d_in[0];
    const float* Lr  = (const float*)d_in[1];
    const float* Li  = (const float*)d_in[2];
    const float* Pr  = (const float*)d_in[3];
    const float* Pi  = (const float*)d_in[4];
    const float* Br  = (const float*)d_in[5];
    const float* Bi  = (const float*)d_in[6];
    const float* Cr  = (const float*)d_in[7];
    const float* Ci  = (const float*)d_in[8];
    const float* ldt = (const float*)d_in[9];
    const float* D   = (const float*)d_in[10];
    float* y = (float*)d_out;

    const size_t smem = (size_t)SPAD * sizeof(float2);   // 34816 B

    zero_flags<<<1, HCH>>>();
    fused_kernel<<<HCH + (HCH / 2) * (BS / 2), 256, smem>>>(
        u, Lr, Li, Pr, Pi, Br, Bi, Cr, Ci, ldt, D, y);
}

// round 17
// speedup vs baseline: 1.5000x; 1.5000x over previous
#include <cuda_runtime.h>
#include <math.h>

#define HCH  512
#define NST  64
#define BS   8
#define LSEQ 2048
#define NFFT 4096
#define SIDX(i) ((i) + ((i) >> 4))
#define SPAD (NFFT + (NFFT >> 4))   // 4352 float2 = 34816 B

// per-channel spectrum, layout [h][j*256 + t] holding bit-rev position p=16t+j
__device__ float2 d_Kf[(size_t)HCH * NFFT];
// per-channel ready flags + per-pair consumed counters (self-resetting:
// zero-initialized at module load; restored to zero by the 4th consumer,
// so every graph replay sees the same initial state)
__device__ int d_flags[HCH];
__device__ int d_cons[HCH / 2];

// W16^m = exp(-2*pi*i*m/16), m=0..7
__constant__ float2 C16[8] = {
    { 1.0f,           0.0f},
    { 0.92387953251f, -0.38268343236f},
    { 0.70710678119f, -0.70710678119f},
    { 0.38268343236f, -0.92387953251f},
    { 0.0f,          -1.0f},
    {-0.38268343236f, -0.92387953251f},
    {-0.70710678119f, -0.70710678119f},
    {-0.92387953251f, -0.38268343236f},
};
// W8^m = exp(-2*pi*i*m/8), m=0..3
__constant__ float2 C8[4] = {
    { 1.0f,           0.0f},
    { 0.70710678119f, -0.70710678119f},
    { 0.0f,          -1.0f},
    {-0.70710678119f, -0.70710678119f},
};

typedef unsigned long long u64c;

// ---- packed f32x2 helpers (sm_100a) ----
__device__ __forceinline__ u64c pk2(float lo, float hi) {
    u64c r; asm("mov.b64 %0, {%1, %2};" : "=l"(r) : "f"(lo), "f"(hi)); return r;
}
__device__ __forceinline__ float2 unpk2(u64c v) {
    float lo, hi; asm("mov.b64 {%0, %1}, %2;" : "=f"(lo), "=f"(hi) : "l"(v));
    return make_float2(lo, hi);
}
__device__ __forceinline__ u64c ffma2_(u64c a, u64c b, u64c c) {
    u64c r; asm("fma.rn.f32x2 %0, %1, %2, %3;" : "=l"(r) : "l"(a), "l"(b), "l"(c));
    return r;
}

__device__ __forceinline__ float2 cmul(float2 a, float2 b) {
    return make_float2(fmaf(a.x, b.x, -a.y * b.y), fmaf(a.x, b.y, a.y * b.x));
}
__device__ __forceinline__ float2 cmulj(float2 a, float2 b) {   // a * conj(b)
    return make_float2(fmaf(a.x, b.x, a.y * b.y), fmaf(a.y, b.x, -a.x * b.y));
}
__device__ __forceinline__ float2 cadd(float2 a, float2 b) { return make_float2(a.x + b.x, a.y + b.y); }
__device__ __forceinline__ float2 csub(float2 a, float2 b) { return make_float2(a.x - b.x, a.y - b.y); }

__device__ __forceinline__ float2 tw4096(int j) {
    float s, c;
    sincospif((float)j * (1.0f / 2048.0f), &s, &c);
    return make_float2(c, -s);
}
__device__ __forceinline__ float2 tw2048(int j) {
    float s, c;
    sincospif((float)j * (1.0f / 1024.0f), &s, &c);
    return make_float2(c, -s);
}

// ---------------------------------------------------------------------------
// Register FFT blocks. fwd16/inv16 = 4 radix-2 DIF/DIT stages; fwd8/inv8 = 3.
// Composition of DIF passes => position p holds frequency brev(p).
// ---------------------------------------------------------------------------
__device__ __forceinline__ void fwd16(float2* v, float2 w1) {
    float2 w2 = cmul(w1, w1), w4 = cmul(w2, w2), w8 = cmul(w4, w4);
#pragma unroll
    for (int j = 0; j < 8; j++) {
        float2 tw = cmul(w1, C16[j]);
        float2 a = v[j], bb = v[j + 8];
        v[j] = cadd(a, bb);
        v[j + 8] = cmul(csub(a, bb), tw);
    }
#pragma unroll
    for (int g = 0; g < 16; g += 8)
#pragma unroll
        for (int j = 0; j < 4; j++) {
            float2 tw = cmul(w2, C16[2 * j]);
            float2 a = v[g + j], bb = v[g + j + 4];
            v[g + j] = cadd(a, bb);
            v[g + j + 4] = cmul(csub(a, bb), tw);
        }
#pragma unroll
    for (int g = 0; g < 16; g += 4)
#pragma unroll
        for (int j = 0; j < 2; j++) {
            float2 tw = cmul(w4, C16[4 * j]);
            float2 a = v[g + j], bb = v[g + j + 2];
            v[g + j] = cadd(a, bb);
            v[g + j + 2] = cmul(csub(a, bb), tw);
        }
#pragma unroll
    for (int g = 0; g < 16; g += 2) {
        float2 a = v[g], bb = v[g + 1];
        v[g] = cadd(a, bb);
        v[g + 1] = cmul(csub(a, bb), w8);
    }
}

// Zero-padded variant: v[8..15] implicitly zero on entry (not read).
__device__ __forceinline__ void fwd16z(float2* v, float2 w1) {
    float2 w2 = cmul(w1, w1), w4 = cmul(w2, w2), w8 = cmul(w4, w4);
#pragma unroll
    for (int j = 0; j < 8; j++) {
        float2 tw = cmul(w1, C16[j]);
        v[j + 8] = cmul(v[j], tw);     // a + 0, (a - 0)*tw
    }
#pragma unroll
    for (int g = 0; g < 16; g += 8)
#pragma unroll
        for (int j = 0; j < 4; j++) {
            float2 tw = cmul(w2, C16[2 * j]);
            float2 a = v[g + j], bb = v[g + j + 4];
            v[g + j] = cadd(a, bb);
            v[g + j + 4] = cmul(csub(a, bb), tw);
        }
#pragma unroll
    for (int g = 0; g < 16; g += 4)
#pragma unroll
        for (int j = 0; j < 2; j++) {
            float2 tw = cmul(w4, C16[4 * j]);
            float2 a = v[g + j], bb = v[g + j + 2];
            v[g + j] = cadd(a, bb);
            v[g + j + 2] = cmul(csub(a, bb), tw);
        }
#pragma unroll
    for (int g = 0; g < 16; g += 2) {
        float2 a = v[g], bb = v[g + 1];
        v[g] = cadd(a, bb);
        v[g + 1] = cmul(csub(a, bb), w8);
    }
}

__device__ __forceinline__ void inv16(float2* v, float2 w1) {
    float2 c1 = make_float2(w1.x, -w1.y);
    float2 c2 = cmul(c1, c1), c4 = cmul(c2, c2), c8 = cmul(c4, c4);
#pragma unroll
    for (int g = 0; g < 16; g += 2) {
        float2 tb = cmul(v[g + 1], c8);
        float2 a = v[g];
        v[g] = cadd(a, tb);
        v[g + 1] = csub(a, tb);
    }
#pragma unroll
    for (int g = 0; g < 16; g += 4)
#pragma unroll
        for (int j = 0; j < 2; j++) {
            float2 tw = cmulj(c4, C16[4 * j]);
            float2 tb = cmul(v[g + j + 2], tw);
            float2 a = v[g + j];
            v[g + j] = cadd(a, tb);
            v[g + j + 2] = csub(a, tb);
        }
#pragma unroll
    for (int g = 0; g < 16; g += 8)
#pragma unroll
        for (int j = 0; j < 4; j++) {
            float2 tw = cmulj(c2, C16[2 * j]);
            float2 tb = cmul(v[g + j + 4], tw);
            float2 a = v[g + j];
            v[g + j] = cadd(a, tb);
            v[g + j + 4] = csub(a, tb);
        }
#pragma unroll
    for (int j = 0; j < 8; j++) {
        float2 tw = cmulj(c1, C16[j]);
        float2 tb = cmul(v[j + 8], tw);
        float2 a = v[j];
        v[j] = cadd(a, tb);
        v[j + 8] = csub(a, tb);
    }
}

__device__ __forceinline__ void fwd8(float2* v, float2 w1) {
    float2 w2 = cmul(w1, w1), w4 = cmul(w2, w2);
#pragma unroll
    for (int j = 0; j < 4; j++) {
        float2 tw = cmul(w1, C8[j]);
        float2 a = v[j], bb = v[j + 4];
        v[j] = cadd(a, bb);
        v[j + 4] = cmul(csub(a, bb), tw);
    }
#pragma unroll
    for (int g = 0; g < 8; g += 4)
#pragma unroll
        for (int j = 0; j < 2; j++) {
            float2 tw = cmul(w2, C8[2 * j]);
            float2 a = v[g + j], bb = v[g + j + 2];
            v[g + j] = cadd(a, bb);
            v[g + j + 2] = cmul(csub(a, bb), tw);
        }
#pragma unroll
    for (int g = 0; g < 8; g += 2) {
        float2 a = v[g], bb = v[g + 1];
        v[g] = cadd(a, bb);
        v[g + 1] = cmul(csub(a, bb), w4);
    }
}

__device__ __forceinline__ void inv8(float2* v, float2 w1) {
    float2 c1 = make_float2(w1.x, -w1.y);
    float2 c2 = cmul(c1, c1), c4 = cmul(c2, c2);
#pragma unroll
    for (int g = 0; g < 8; g += 2) {
        float2 tb = cmul(v[g + 1], c4);
        float2 a = v[g];
        v[g] = cadd(a, tb);
        v[g + 1] = csub(a, tb);
    }
#pragma unroll
    for (int g = 0; g < 8; g += 4)
#pragma unroll
        for (int j = 0; j < 2; j++) {
            float2 tw = cmulj(c2, C8[2 * j]);
            float2 tb = cmul(v[g + j + 2], tw);
            float2 a = v[g + j];
            v[g + j] = cadd(a, tb);
            v[g + j + 2] = csub(a, tb);
        }
#pragma unroll
    for (int j = 0; j < 4; j++) {
        float2 tw = cmulj(c1, C8[j]);
        float2 tb = cmul(v[j + 4], tw);
        float2 a = v[j];
        v[j] = cadd(a, tb);
        v[j + 4] = csub(a, tb);
    }
}

// One full 4096 FFT-conv-IFFT on v[16] through smem x.
// Input: v[0..7] data, v[8..15] implicitly zero (zero-padded signal).
__device__ __forceinline__ void fft_conv_4096(
        float2* v, float2* x, int t, int base2,
        float2 w1, float2 wp2, const float2* __restrict__ kf) {
    fwd16z(v, w1);
#pragma unroll
    for (int j = 0; j < 16; j++) x[SIDX(t + 256 * j)] = v[j];
    __syncthreads();
#pragma unroll
    for (int j = 0; j < 16; j++) v[j] = x[SIDX(base2 + 16 * j)];
    fwd16(v, wp2);
#pragma unroll
    for (int j = 0; j < 16; j++) x[SIDX(base2 + 16 * j)] = v[j];
    __syncthreads();
#pragma unroll
    for (int j = 0; j < 16; j++) v[j] = x[SIDX(16 * t + j)];
    fwd16(v, make_float2(1.f, 0.f));
#pragma unroll
    for (int j = 0; j < 16; j++) v[j] = cmul(v[j], kf[j * 256 + t]);
    inv16(v, make_float2(1.f, 0.f));
#pragma unroll
    for (int j = 0; j < 16; j++) x[SIDX(16 * t + j)] = v[j];
    __syncthreads();
#pragma unroll
    for (int j = 0; j < 16; j++) v[j] = x[SIDX(base2 + 16 * j)];
    inv16(v, wp2);
#pragma unroll
    for (int j = 0; j < 16; j++) x[SIDX(base2 + 16 * j)] = v[j];
    __syncthreads();
#pragma unroll
    for (int j = 0; j < 16; j++) v[j] = x[SIDX(t + 256 * j)];
    inv16(v, w1);
}

// ---------------------------------------------------------------------------
// Fused kernel: bids [0, HCH) = spec; bids [HCH, HCH+1024) = conv (flag-gated).
// Spec: zero-pad split (even half of K^ = Hermitian-projected at_roots; odd
// half = modulated 2048-FFT). __launch_bounds__(256, 2): R15 config (the
// (256,3) cap spilled spec to local memory — R16 regression).
// ---------------------------------------------------------------------------
__global__ void __launch_bounds__(256, 2) fused_kernel(
        const float* __restrict__ u,
        const float* __restrict__ Lr, const float* __restrict__ Li,
        const float* __restrict__ Pr, const float* __restrict__ Pi,
        const float* __restrict__ Br, const float* __restrict__ Bi,
        const float* __restrict__ Cr, const float* __restrict__ Ci,
        const float* __restrict__ logdt, const float* __restrict__ D,
        float* __restrict__ y) {
    extern __shared__ float2 x[];   // SPAD float2

    if (blockIdx.x < HCH) {
        // ================= SPEC branch =================
        const int h   = blockIdx.x;
        const int tid = threadIdx.x;

        __shared__ float2 lam[NST], w00[NST];
        __shared__ __align__(16) u64c WT[NST * 14];

        if (tid < NST) {
            int n = tid;
            lam[n] = make_float2(Lr[n], Li[n]);
            float2 P  = make_float2(Pr[n], Pi[n]);
            float2 Bv = make_float2(Br[n], Bi[n]);
            float2 Cc = make_float2(Cr[h * NST + n], -Ci[h * NST + n]);
            w00[n] = cmul(Cc, Bv);
        }
        __syncthreads();
        // Build packed a/b weight tables (a-lane n, b-lane m=63-n)
        if (tid < NST) {
            int n = tid, m = NST - 1 - n;
            u64c* T = &WT[n * 14];
            float2 Pn = make_float2(Pr[n], Pi[n]);
            float2 Pm = make_float2(Pr[m], Pi[m]);
            float2 Bn = make_float2(Br[n], Bi[n]);
            float2 Bm = make_float2(Br[m], Bi[m]);
            float2 Ccn = make_float2(Cr[h * NST + n], -Ci[h * NST + n]);
            float2 Ccm = make_float2(Cr[h * NST + m], -Ci[h * NST + m]);
            float2 wn, wm;
            wn = cmul(Ccn, Bn); wm = cmul(Ccm, Bm);          // w00
            T[0]  = pk2(wn.x, wm.x);  T[1]  = pk2(-wn.y, wm.y);
            T[2]  = pk2(wn.x, -wm.x); T[3]  = pk2(wn.y, wm.y);
            wn = cmul(Ccn, Pn); wm = cmul(Ccm, Pm);          // w01
            T[4]  = pk2(wn.x, wm.x);  T[5]  = pk2(-wn.y, wm.y);
            T[6]  = pk2(wn.x, -wm.x); T[7]  = pk2(wn.y, wm.y);
            float2 Qcn = make_float2(Pn.x, -Pn.y);
            float2 Qcm = make_float2(Pm.x, -Pm.y);
            wn = cmul(Qcn, Bn); wm = cmul(Qcm, Bm);          // w10
            T[8]  = pk2(wn.x, wm.x);  T[9]  = pk2(-wn.y, wm.y);
            T[10] = pk2(wn.x, -wm.x); T[11] = pk2(wn.y, wm.y);
            float w11n = Pn.x * Pn.x + Pn.y * Pn.y;
            float w11m = Pm.x * Pm.x + Pm.y * Pm.y;
            T[12] = pk2(w11n, w11m);
            T[13] = pk2(w11n, -w11m);
        }
        __syncthreads();

        const float dt = expf(logdt[h]);
        const float g0 = 2.0f / dt;

        // ---- Ã(l) = (A(l)+conj(A(2048-l)))/2, stored at brev11 positions ----
        for (int l = tid; l < 1024; l += blockDim.x) {
            float ss, cc;
            sincospif((float)l * (1.0f / 1024.0f), &ss, &cc);
            float2 om = make_float2(cc, -ss);
            float2 den = make_float2(1.f + om.x, om.y);
            float2 num = make_float2(1.f - om.x, -om.y);
            float idl  = __fdividef(1.f, den.x * den.x + den.y * den.y);
            float2 c2  = make_float2(2.f * den.x * idl, -2.f * den.y * idl);
            float2 gf  = cmul(num, make_float2(den.x, -den.y));
            float2 g   = make_float2(g0 * gf.x * idl, g0 * gf.y * idl);

            u64c K00R = 0, K00I = 0, K01R = 0, K01I = 0;
            u64c K10R = 0, K10I = 0, K11R = 0, K11I = 0;
#pragma unroll 4
            for (int n = 0; n < NST; n++) {
                float2 L = lam[n];
                float dx = g.x - L.x;
                float dy = g.y - L.y;
                float iv = __fdividef(1.f, fmaf(dx, dx, dy * dy));
                float rx = dx * iv;
                float ry = -dy * iv;
                u64c RX = pk2(rx, rx);
                u64c RY = pk2(ry, ry);
                const u64c* T = &WT[n * 14];
                ulonglong2 t0 = *(const ulonglong2*)(T + 0);
                ulonglong2 t1 = *(const ulonglong2*)(T + 2);
                ulonglong2 t2 = *(const ulonglong2*)(T + 4);
                ulonglong2 t3 = *(const ulonglong2*)(T + 6);
                ulonglong2 t4 = *(const ulonglong2*)(T + 8);
                ulonglong2 t5 = *(const ulonglong2*)(T + 10);
                ulonglong2 t6 = *(const ulonglong2*)(T + 12);
                K00R = ffma2_(t0.x, RX, K00R);  K00R = ffma2_(t0.y, RY, K00R);
                K00I = ffma2_(t1.x, RY, K00I);  K00I = ffma2_(t1.y, RX, K00I);
                K01R = ffma2_(t2.x, RX, K01R);  K01R = ffma2_(t2.y, RY, K01R);
                K01I = ffma2_(t3.x, RY, K01I);  K01I = ffma2_(t3.y, RX, K01I);
                K10R = ffma2_(t4.x, RX, K10R);  K10R = ffma2_(t4.y, RY, K10R);
                K10I = ffma2_(t5.x, RY, K10I);  K10I = ffma2_(t5.y, RX, K10I);
                K11R = ffma2_(t6.x, RX, K11R);
                K11I = ffma2_(t6.y, RY, K11I);
            }
            float2 r00 = unpk2(K00R), i00 = unpk2(K00I);
            float2 r01 = unpk2(K01R), i01 = unpk2(K01I);
            float2 r10 = unpk2(K10R), i10 = unpk2(K10I);
            float2 r11 = unpk2(K11R), i11 = unpk2(K11I);
            float2 a00 = make_float2(r00.x, i00.x), b00 = make_float2(r00.y, i00.y);
            float2 a01 = make_float2(r01.x, i01.x), b01 = make_float2(r01.y, i01.y);
            float2 a10 = make_float2(r10.x, i10.x), b10 = make_float2(r10.y, i10.y);
            float2 a11 = make_float2(r11.x, i11.x), b11 = make_float2(r11.y, i11.y);

            float2 Aa;
            {   // A[l]
                float2 onep = make_float2(1.f + a11.x, a11.y);
                float  ip   = __fdividef(1.f, onep.x * onep.x + onep.y * onep.y);
                float2 invd = make_float2(onep.x * ip, -onep.y * ip);
                float2 t2   = cmul(cmul(a01, a10), invd);
                Aa = cmul(c2, csub(a00, t2));
            }
            if (l != 0) {
                float2 Ab;   // A[2048-l]
                float2 c2c  = make_float2(c2.x, -c2.y);
                float2 onep = make_float2(1.f + b11.x, b11.y);
                float  ip   = __fdividef(1.f, onep.x * onep.x + onep.y * onep.y);
                float2 invd = make_float2(onep.x * ip, -onep.y * ip);
                float2 t2   = cmul(cmul(b01, b10), invd);
                Ab = cmul(c2c, csub(b00, t2));
                // Hermitian projection: Ã(l), Ã(2048-l)=conj(Ã(l))
                float2 At = make_float2(0.5f * (Aa.x + Ab.x), 0.5f * (Aa.y - Ab.y));
                int rl  = __brev(l) >> 21;
                int rl2 = __brev(2048 - l) >> 21;
                x[SIDX(rl)]  = At;
                x[SIDX(rl2)] = make_float2(At.x, -At.y);
            } else {
                x[SIDX(0)] = make_float2(Aa.x, 0.f);
            }
        }
        if (tid == 0) {
            // l = 1024: omega = -1 limit; Ã(1024) = Re(A(1024)); brev11(1024)=1
            float2 s = make_float2(0.f, 0.f);
            for (int n = 0; n < NST; n++) s = cadd(s, w00[n]);
            x[SIDX(1)] = make_float2(0.5f * dt * s.x, 0.f);
        }
        __syncthreads();

        float2* kf = d_Kf + (size_t)h * NFFT;

        // ---- EVEN half of K^: kf[j*256+t] = Ã at position p=16t+j (t<128) ----
#pragma unroll
        for (int s = 0; s < 8; s++) {
            int e  = tid + 256 * s;          // 0..2047
            int j  = e >> 7;                 // 0..15
            int tt = e & 127;                // 0..127
            kf[j * 256 + tt] = x[SIDX(16 * tt + j)];
        }
        __syncthreads();

        // ---- IFFT-2048 (inv8 {8t+j}, inv16 {baseB+8j}, inv16 {t+128j}) ----
        {
            float2 v8[8];
#pragma unroll
            for (int j = 0; j < 8; j++) v8[j] = x[SIDX(8 * tid + j)];
            inv8(v8, make_float2(1.f, 0.f));
#pragma unroll
            for (int j = 0; j < 8; j++) x[SIDX(8 * tid + j)] = v8[j];
        }
        __syncthreads();
        {
            float2 v[16];
            if (tid < 128) {
                int baseB = ((tid >> 3) << 7) + (tid & 7);
#pragma unroll
                for (int j = 0; j < 16; j++) v[j] = x[SIDX(baseB + 8 * j)];
                inv16(v, tw2048(16 * (tid & 7)));
#pragma unroll
                for (int j = 0; j < 16; j++) x[SIDX(baseB + 8 * j)] = v[j];
            }
            __syncthreads();
            if (tid < 128) {
#pragma unroll
                for (int j = 0; j < 16; j++) v[j] = x[SIDX(tid + 128 * j)];
                inv16(v, tw2048(tid));
                // scale + realify + modulate by W4096^n (n = tid + 128*j)
                const float  sc   = 1.0f / 2048.0f;
                const float2 C128 = make_float2(0.98078528040323044913f,
                                                -0.19509032201612826785f); // W4096^128
                float2 wn = tw4096(tid);
#pragma unroll
                for (int j = 0; j < 16; j++) {
                    float kk = v[j].x * sc;
                    x[SIDX(tid + 128 * j)] = make_float2(kk * wn.x, kk * wn.y);
                    wn = cmul(wn, C128);
                }
            }
        }
        __syncthreads();

        // ---- forward FFT-2048 on modulated K (natural -> brev11 positions) ----
        {
            float2 v[16];
            if (tid < 128) {
#pragma unroll
                for (int j = 0; j < 16; j++) v[j] = x[SIDX(tid + 128 * j)];
                fwd16(v, tw2048(tid));
#pragma unroll
                for (int j = 0; j < 16; j++) x[SIDX(tid + 128 * j)] = v[j];
            }
            __syncthreads();
            if (tid < 128) {
                int baseB = ((tid >> 3) << 7) + (tid & 7);
#pragma unroll
                for (int j = 0; j < 16; j++) v[j] = x[SIDX(baseB + 8 * j)];
                fwd16(v, tw2048((tid & 7) << 4));
#pragma unroll
                for (int j = 0; j < 16; j++) x[SIDX(baseB + 8 * j)] = v[j];
            }
            __syncthreads();
        }
        {
            float2 v8[8];
#pragma unroll
            for (int j = 0; j < 8; j++) v8[j] = x[SIDX(8 * tid + j)];
            fwd8(v8, make_float2(1.f, 0.f));
            // ---- ODD half of K^: position q=8*tid+j -> kf[(q&15)*256+128+(q>>4)]
#pragma unroll
            for (int j = 0; j < 8; j++) {
                int q = 8 * tid + j;
                kf[(q & 15) * 256 + 128 + (q >> 4)] = v8[j];
            }
        }

        // release
        __syncthreads();
        if (tid == 0) {
            __threadfence();
            atomicExch(&d_flags[h], 1);
        }
    } else {
        // ================= CONV branch =================
        const int i  = blockIdx.x - HCH;
        const int hp = i & (HCH / 2 - 1);      // 0..255
        const int bp = i >> 8;                 // 0..3
        const int t  = threadIdx.x;

        if (t == 0) {
            while (atomicAdd(&d_flags[2 * hp], 0) == 0) __nanosleep(200);
            while (atomicAdd(&d_flags[2 * hp + 1], 0) == 0) __nanosleep(200);
            __threadfence();
            // self-resetting protocol: 4th consumer (bp=0..3) restores state
            int old = atomicAdd(&d_cons[hp], 1);
            if (old == 3) {
                atomicExch(&d_flags[2 * hp], 0);
                atomicExch(&d_flags[2 * hp + 1], 0);
                atomicExch(&d_cons[hp], 0);
            }
        }
        __syncthreads();

        const float2* ua2 = (const float2*)(u + (size_t)(2 * bp) * LSEQ * HCH) + hp;
        const float2* ub2 = (const float2*)(u + (size_t)(2 * bp + 1) * LSEQ * HCH) + hp;

        float2 v[16], z1[8], y0[8];
#pragma unroll
        for (int j = 0; j < 8; j++) {
            size_t idx = (size_t)(t + 256 * j) * (HCH / 2);
            float2 la = ua2[idx];
            float2 lb = ub2[idx];
            v[j]  = make_float2(la.x, lb.x);   // channel 2hp:   b0 + i*b1
            z1[j] = make_float2(la.y, lb.y);   // channel 2hp+1: b0 + i*b1
        }
        // v[8..15] implicitly zero (fwd16z)

        const float2 w1  = tw4096(t);
        const float2 wp2 = tw4096((t & 15) << 4);
        const int base2  = ((t >> 4) << 8) + (t & 15);

        fft_conv_4096(v, x, t, base2, w1, wp2, d_Kf + (size_t)(2 * hp) * NFFT);
#pragma unroll
        for (int j = 0; j < 8; j++) y0[j] = v[j];

#pragma unroll
        for (int j = 0; j < 8; j++) v[j] = z1[j];
        fft_conv_4096(v, x, t, base2, w1, wp2, d_Kf + (size_t)(2 * hp + 1) * NFFT);

        const float D0  = D[2 * hp];
        const float D1  = D[2 * hp + 1];
        const float inv = 1.0f / (float)NFFT;
        float2* ya2 = (float2*)(y + (size_t)(2 * bp) * LSEQ * HCH) + hp;
        float2* yb2 = (float2*)(y + (size_t)(2 * bp + 1) * LSEQ * HCH) + hp;
#pragma unroll
        for (int j = 0; j < 8; j++) {
            size_t idx = (size_t)(t + 256 * j) * (HCH / 2);
            float2 la = ua2[idx];
            float2 lb = ub2[idx];
            float2 oa, ob;
            oa.x = fmaf(y0[j].x, inv, la.x * D0);
            oa.y = fmaf(v[j].x,  inv, la.y * D1);
            ob.x = fmaf(y0[j].y, inv, lb.x * D0);
            ob.y = fmaf(v[j].y,  inv, lb.y * D1);
            ya2[idx] = oa;
            yb2[idx] = ob;
        }
    }
}

// ---------------------------------------------------------------------------
extern "C" void kernel_launch(void* const* d_in, const int* in_sizes, int n_in,
                              void* d_out, int out_size) {
    const float* u   = (const float*)d_in[0];
    const float* Lr  = (const float*)d_in[1];
    const float* Li  = (const float*)d_in[2];
    const float* Pr  = (const float*)d_in[3];
    const float* Pi  = (const float*)d_in[4];
    const float* Br  = (const float*)d_in[5];
    const float* Bi  = (const float*)d_in[6];
    const float* Cr  = (const float*)d_in[7];
    const float* Ci  = (const float*)d_in[8];
    const float* ldt = (const float*)d_in[9];
    const float* D   = (const float*)d_in[10];
    float* y = (float*)d_out;

    const size_t smem = (size_t)SPAD * sizeof(float2);   // 34816 B

    fused_kernel<<<HCH + (HCH / 2) * (BS / 2), 256, smem>>>(
        u, Lr, Li, Pr, Pi, Br, Bi, Cr, Ci, ldt, D, y);
}